// round 3
// baseline (speedup 1.0000x reference)
#include <cuda_runtime.h>
#include <cuda_bf16.h>

#define BATCH 256
#define PPAIR 1024
#define TPTS  100
#define NGRID 65536
#define KMAX  2

__global__ __launch_bounds__(1024, 2)
void pl_kernel(const float* __restrict__ inputs,
               const int*   __restrict__ dim_idx,
               const int*   __restrict__ birth_loc,
               const int*   __restrict__ death_loc,
               float* __restrict__ land,    // [B, 2, T, 2]
               float* __restrict__ trange)  // [B, 4]
{
    __shared__ __align__(16) float2 pairs[2][PPAIR]; // compacted (mid, half) per dim
    __shared__ int    s_dim[PPAIR];
    __shared__ float  s_b[PPAIR], s_d[PPAIR];
    __shared__ float2 s_part[2][4][128];             // [dim][chunk][t] partial top-2
    __shared__ int    s_cnt[2];
    __shared__ float  s_tmin[2], s_tmax[2];
    __shared__ unsigned s_max[2];

    const int b    = blockIdx.x;
    const int tid  = threadIdx.x;
    const int lane = tid & 31;
    const int w    = tid >> 5;
    if (tid < 2) { s_cnt[tid] = 0; s_max[tid] = 0u; }
    __syncthreads();

    const float* __restrict__ row = inputs + (size_t)b * NGRID;

    // ---- Phase 1: gather + warp-aggregated per-dim compaction (1 pair/thread)
    {
        const int p  = tid;
        const int d  = dim_idx  [b * PPAIR + p];
        const float vb = __ldg(row + birth_loc[b * PPAIR + p]);
        const float vd = __ldg(row + death_loc[b * PPAIR + p]);
        s_dim[p] = d; s_b[p] = vb; s_d[p] = vd;

        unsigned mask1  = __ballot_sync(0xffffffffu, d == 1);
        unsigned mymask = d ? mask1 : ~mask1;
        unsigned lt     = (1u << lane) - 1u;
        int rank   = __popc(mymask & lt);
        int leader = __ffs(mymask) - 1;
        int base = 0;
        if (lane == leader) base = atomicAdd(&s_cnt[d], __popc(mymask));
        base = __shfl_sync(0xffffffffu, base, leader);
        pairs[d][base + rank] = make_float2(0.5f * (vb + vd),   // mid
                                            0.5f * (vd - vb));  // half-width
    }
    __syncthreads();

    // ---- t-range from the FIRST KMAX valid pairs in original order (cheap, ~4 iters)
    if (tid < 2) {
        const int dim = tid;
        float tmin = 1e30f, tmax = -1e30f;
        int found = 0;
        for (int p = 0; p < PPAIR && found < KMAX; p++) {
            if (s_dim[p] == dim) {
                tmin = fminf(tmin, s_b[p]);
                tmax = fmaxf(tmax, s_d[p]);
                found++;
            }
        }
        if (s_cnt[dim] == 0) { tmin = 0.0f; tmax = 0.0f; }
        s_tmin[dim] = tmin; s_tmax[dim] = tmax;
    }
    __syncthreads();

    // ---- Phase 2: lane = t (broadcast pair reads), warps split {dim} x {tgrp} x {chunk}
    // 32 warps = 2 dims * 4 t-groups * 4 pair-chunks
    {
        const int dim   = w >> 4;         // warp-uniform
        const int tgrp  = (w >> 2) & 3;
        const int chunk = w & 3;
        const int t     = tgrp * 32 + lane;   // 0..127 (valid if < TPTS)

        const int   cnt  = s_cnt[dim];
        const float tmin = s_tmin[dim];
        const float tmax = s_tmax[dim];
        const float tv   = tmin + (tmax - tmin) *
                           ((float)t * (1.0f / (float)(TPTS - 1)));

        const float4* __restrict__ p4 = (const float4*)pairs[dim];
        const int n4 = cnt >> 1;
        float m1a = 0.0f, m2a = 0.0f, m1b = 0.0f, m2b = 0.0f;
        // tent(p,t) = half - |tv - mid|; clamp-to-0 implicit (accums start at 0)
        #pragma unroll 2
        for (int i = chunk; i < n4; i += 4) {
            float4 q  = p4[i];                 // warp-uniform address -> broadcast
            float va  = q.y - fabsf(tv - q.x);
            float vb2 = q.w - fabsf(tv - q.z);
            m2a = fmaxf(m2a, fminf(m1a, va));  m1a = fmaxf(m1a, va);
            m2b = fmaxf(m2b, fminf(m1b, vb2)); m1b = fmaxf(m1b, vb2);
        }
        if ((cnt & 1) && chunk == 0) {         // odd tail pair
            float2 mh = pairs[dim][cnt - 1];   // uniform -> broadcast
            float v = mh.y - fabsf(tv - mh.x);
            m2a = fmaxf(m2a, fminf(m1a, v)); m1a = fmaxf(m1a, v);
        }
        // merge the two chains
        float lo = fminf(m1a, m1b);
        float m1 = fmaxf(m1a, m1b);
        float m2 = fmaxf(lo, fmaxf(m2a, m2b));
        s_part[dim][chunk][t] = make_float2(m1, m2);
    }
    __syncthreads();

    // ---- Merge the 4 pair-chunks per (dim, t), write outputs
    if (tid < 256) {
        const int dim = tid >> 7;             // warp-uniform
        const int t   = tid & 127;
        float m1 = 0.0f;
        if (t < TPTS) {
            float2 a = s_part[dim][0][t];
            m1 = a.x; float m2 = a.y;
            #pragma unroll
            for (int c = 1; c < 4; c++) {
                float2 o = s_part[dim][c][t];
                float lo = fminf(m1, o.x);
                m1 = fmaxf(m1, o.x);
                m2 = fmaxf(fmaxf(lo, m2), o.y);
            }
            *(float2*)&land[((size_t)(b * 2 + dim) * TPTS + t) * 2] =
                make_float2(m1, m2);
        }
        unsigned wmax = __reduce_max_sync(0xffffffffu, __float_as_uint(m1));
        if (lane == 0) atomicMax(&s_max[dim], wmax);  // m1 >= 0: bit order OK
    }
    __syncthreads();

    if (tid < 2) {
        bool nz = (s_cnt[tid] > 0) && (__uint_as_float(s_max[tid]) > 0.0f);
        trange[b * 4 + 2 * tid + 0] = nz ? s_tmin[tid] : 0.0f;
        trange[b * 4 + 2 * tid + 1] = nz ? s_tmax[tid] : 0.0f;
    }
}

extern "C" void kernel_launch(void* const* d_in, const int* in_sizes, int n_in,
                              void* d_out, int out_size) {
    const float* inputs    = (const float*)d_in[0];
    const int*   dim_idx   = (const int*)  d_in[1];
    const int*   birth_loc = (const int*)  d_in[2];
    const int*   death_loc = (const int*)  d_in[3];

    float* land   = (float*)d_out;                        // B*2*T*2 = 102400
    float* trange = land + (size_t)BATCH * 2 * TPTS * 2;  // B*4     = 1024

    pl_kernel<<<BATCH, 1024>>>(inputs, dim_idx, birth_loc, death_loc, land, trange);
}